// round 16
// baseline (speedup 1.0000x reference)
#include <cuda_runtime.h>
#include <cuda_fp16.h>
#include <cstdint>
#include <math.h>

#define B_   64
#define T_   512
#define D_   512
#define H_   512
#define MTOT (B_ * T_)          // 32768 GEMM rows

// ---------------------------------------------------------------------------
// Scratch (static __device__ — allocation-guard safe)
// ---------------------------------------------------------------------------
// projections xz, xr, xh in fp16, layout [b*t][h] (+64-step pad: the scan's
// cp.async pipeline prefetches up to 3 stages = 48 steps past the end).
__device__ __half g_proj[3][(size_t)MTOT * H_ + 64 * H_];
// fp16 x
__device__ __half g_A[(size_t)MTOT * D_];
// fp16 W^T (stored [N][K] K-major)
__device__ __half g_WT[3][H_ * D_];

// ---------------------------------------------------------------------------
// helpers
// ---------------------------------------------------------------------------
__device__ __forceinline__ uint32_t smem_u32(const void* p) {
    return (uint32_t)__cvta_generic_to_shared(p);
}

__device__ __forceinline__ void cp16(uint32_t dst, const void* src) {
    asm volatile("cp.async.cg.shared.global [%0], [%1], 16;"
                 :: "r"(dst), "l"(src) : "memory");
}
#define CP_COMMIT() asm volatile("cp.async.commit_group;" ::: "memory")
#define CP_WAIT(n)  asm volatile("cp.async.wait_group %0;" :: "n"(n) : "memory")

__device__ __forceinline__ void ldmatrix_x4(uint32_t& r0, uint32_t& r1,
                                            uint32_t& r2, uint32_t& r3,
                                            uint32_t addr) {
    asm volatile("ldmatrix.sync.aligned.m8n8.x4.shared.b16 {%0,%1,%2,%3}, [%4];"
                 : "=r"(r0), "=r"(r1), "=r"(r2), "=r"(r3) : "r"(addr));
}
__device__ __forceinline__ void mma16816(float* c, const uint32_t* a,
                                         const uint32_t* b) {
    asm volatile(
        "mma.sync.aligned.m16n8k16.row.col.f32.f16.f16.f32 "
        "{%0,%1,%2,%3}, {%4,%5,%6,%7}, {%8,%9}, {%0,%1,%2,%3};"
        : "+f"(c[0]), "+f"(c[1]), "+f"(c[2]), "+f"(c[3])
        : "r"(a[0]), "r"(a[1]), "r"(a[2]), "r"(a[3]), "r"(b[0]), "r"(b[1]));
}

// HW tanh (MUFU.TANH, sm_75+)
__device__ __forceinline__ float tanh_hw(float x) {
    float y;
    asm("tanh.approx.f32 %0, %1;" : "=f"(y) : "f"(x));
    return y;
}

// ---------------------------------------------------------------------------
// Kernel 1: convert x to fp16
// ---------------------------------------------------------------------------
__global__ __launch_bounds__(256)
void convert_x_kernel(const float* __restrict__ x) {
    size_t i = (size_t)blockIdx.x * blockDim.x + threadIdx.x;   // one float4
    float4 v = reinterpret_cast<const float4*>(x)[i];
    __half2* Hp = reinterpret_cast<__half2*>(g_A);
    Hp[2 * i]     = __halves2half2(__float2half_rn(v.x), __float2half_rn(v.y));
    Hp[2 * i + 1] = __halves2half2(__float2half_rn(v.z), __float2half_rn(v.w));
}

// ---------------------------------------------------------------------------
// Kernel 2: transpose weights to fp16 [N][K] via 32x33 smem tile
// (coalesced reads AND writes). grid = (16, 16, 3), block = 256.
// ---------------------------------------------------------------------------
__global__ __launch_bounds__(256)
void convert_w_kernel(const float* __restrict__ kz,
                      const float* __restrict__ kr,
                      const float* __restrict__ kh) {
    __shared__ float tile[32][33];
    const float* W = (blockIdx.z == 0) ? kz : (blockIdx.z == 1) ? kr : kh;
    const int k0 = blockIdx.y * 32;
    const int n0 = blockIdx.x * 32;
    const int tx = threadIdx.x & 31;
    const int ty = threadIdx.x >> 5;     // 0..7
    #pragma unroll
    for (int i = 0; i < 4; ++i)
        tile[ty + i * 8][tx] = W[(size_t)(k0 + ty + i * 8) * H_ + n0 + tx];
    __syncthreads();
    #pragma unroll
    for (int i = 0; i < 4; ++i) {
        int n = ty + i * 8;
        g_WT[blockIdx.z][(size_t)(n0 + n) * D_ + k0 + tx] =
            __float2half_rn(tile[tx][n]);
    }
}

// ---------------------------------------------------------------------------
// Kernel 3: fp16 GEMM via mma.sync.m16n8k16 — R6 geometry + BK=64.
// CTA tile 256x128, 256 threads (8 warps: 4M x 2N, warp tile 64x64):
// 128 MMAs per warp per sync, syncs halved vs R6 (BK=64, NIT=8).
// 3-stage cp.async pipeline; rows 128B data padded to 144B (conflict-free).
// Loads for stage it+2 issued AFTER sync of iter it -> hazard-free.
// K-accumulation order unchanged -> bit-identical results.
// grid = (12, 128): x = mat*4 + ntile, y = mtile (256 rows each).
// ---------------------------------------------------------------------------
#define ROWB      144                        // smem row stride (bytes)
#define A_STAGE   (256 * ROWB)               // 36864 B
#define B_STAGE   (128 * ROWB)               // 18432 B
#define STAGE_B   (A_STAGE + B_STAGE)        // 55296 B
#define GEMM_SMEM (3 * STAGE_B)              // 165888 B (1 CTA/SM)

__global__ __launch_bounds__(256, 1)
void gemm_kernel() {
    extern __shared__ __align__(128) char dsmem[];
    const uint32_t sbase = smem_u32(dsmem);

    const int tid  = threadIdx.x;
    const int lane = tid & 31;
    const int wid  = tid >> 5;
    const int wm   = (wid & 3) * 64;    // warp M offset in tile (4 groups)
    const int wn   = (wid >> 2) * 64;   // warp N offset in tile (2 groups)

    const int mat   = blockIdx.x >> 2;
    const int nBase = (blockIdx.x & 3) * 128;
    const int mBase = blockIdx.y * 256;

    const __half* Ap = g_A + (size_t)mBase * D_;
    const __half* Wp = g_WT[mat] + (size_t)nBase * D_;
    __half* C = g_proj[mat];

    // loaders: A 256 rows x 8 chunks = 2048 (8/thread); B 128 x 8 = 1024 (4/thread)
    const int lrow = tid >> 3;       // base row (0..31), stepped by +32
    const int lseg = tid & 7;        // 16B chunk within 128B row
    auto load_tile = [&](int j) {    // j = k-tile index 0..7 (64 halfs each)
        const int kk = j * 64;
        const uint32_t sa = sbase + (j % 3) * STAGE_B;
        const uint32_t sb = sa + A_STAGE;
        #pragma unroll
        for (int i = 0; i < 8; ++i) {
            int row = lrow + i * 32;
            cp16(sa + row * ROWB + lseg * 16,
                 Ap + (size_t)row * D_ + kk + lseg * 8);
        }
        #pragma unroll
        for (int i = 0; i < 4; ++i) {
            int row = lrow + i * 32;
            cp16(sb + row * ROWB + lseg * 16,
                 Wp + (size_t)row * D_ + kk + lseg * 8);
        }
    };

    // ldmatrix per-lane offsets (row stride 144B; k16 halves 32B apart)
    const int a_off = (wm + (lane & 15)) * ROWB + (lane >> 4) * 16;
    const int b_off = (wn + (lane & 7) + ((lane >> 4) & 1) * 8) * ROWB
                    + ((lane >> 3) & 1) * 16;

    float acc[4][8][4];
    #pragma unroll
    for (int i = 0; i < 4; ++i)
        #pragma unroll
        for (int j = 0; j < 8; ++j)
            #pragma unroll
            for (int e = 0; e < 4; ++e) acc[i][j][e] = 0.0f;

    constexpr int NIT = 8;   // 512 / BK64
    load_tile(0); CP_COMMIT();
    load_tile(1); CP_COMMIT();

    for (int it = 0; it < NIT; ++it) {
        CP_WAIT(1);                // group 'it' (stage it) complete
        __syncthreads();           // all threads past iter it-1 compute

        // prefetch stage it+2 into buffer (it+2)%3 == (it-1)%3 — every
        // thread is past sync(it), hence past its it-1 compute: drained.
        if (it + 2 < NIT) load_tile(it + 2);
        CP_COMMIT();               // empty commits at tail keep wait math uniform

        const uint32_t sa = sbase + (it % 3) * STAGE_B;
        const uint32_t aB = sa + a_off;
        const uint32_t bB = sa + A_STAGE + b_off;

        #pragma unroll
        for (int ks = 0; ks < 4; ++ks) {          // four k16 steps in BK=64
            uint32_t af[4][4], bq[4][4];
            #pragma unroll
            for (int mt = 0; mt < 4; ++mt)
                ldmatrix_x4(af[mt][0], af[mt][1], af[mt][2], af[mt][3],
                            aB + mt * 16 * ROWB + ks * 32);
            #pragma unroll
            for (int np = 0; np < 4; ++np)        // each x4 = two n8 b-frags
                ldmatrix_x4(bq[np][0], bq[np][1], bq[np][2], bq[np][3],
                            bB + np * 16 * ROWB + ks * 32);
            #pragma unroll
            for (int mt = 0; mt < 4; ++mt)
                #pragma unroll
                for (int nt = 0; nt < 8; ++nt)
                    mma16816(acc[mt][nt], af[mt], &bq[nt >> 1][(nt & 1) * 2]);
        }
    }

    // epilogue: pack adjacent col pairs to half2 (4B stores)
    const int row0 = mBase + wm + (lane >> 2);
    const int col0 = nBase + wn + (lane & 3) * 2;
    #pragma unroll
    for (int mt = 0; mt < 4; ++mt) {
        #pragma unroll
        for (int nt = 0; nt < 8; ++nt) {
            __half* p = C + (size_t)(row0 + mt * 16) * H_ + col0 + nt * 8;
            *reinterpret_cast<__half2*>(p) =
                __floats2half2_rn(acc[mt][nt][0], acc[mt][nt][1]);
            *reinterpret_cast<__half2*>(p + 8 * H_) =
                __floats2half2_rn(acc[mt][nt][2], acc[mt][nt][3]);
        }
    }
}

// ---------------------------------------------------------------------------
// Kernel 4: diagonal recurrence scan, cp.async-staged (R12 version, frozen).
// ---------------------------------------------------------------------------
#define SC_STAGE 12288                     // 3 mats * 16 t * 256 B
#define SC_SMEM  (4 * SC_STAGE)            // 49152 B

__global__ __launch_bounds__(128)
void scan_kernel(const float* __restrict__ h0,
                 const float* __restrict__ mz, const float* __restrict__ mr,
                 const float* __restrict__ bz, const float* __restrict__ br,
                 float* __restrict__ out)
{
    extern __shared__ __align__(16) char ssm[];
    const uint32_t sb = smem_u32(ssm);
    const int tid = threadIdx.x;
    const int b   = blockIdx.x >> 2;        // 4 blocks per batch
    const int hb  = blockIdx.x & 3;
    const int h   = hb * 128 + tid;

    float hv = h0[(size_t)b * H_ + h];
    const float mzv = mz[h];
    const float mrv = mr[h];
    const float bzv = bz[h];
    const float brv = br[h];

    const size_t rowb = (size_t)b * T_ * H_ + (size_t)hb * 128;

    auto load_stage = [&](int s) {          // s = t-chunk index (16 steps)
        const uint32_t dst = sb + (s & 3) * SC_STAGE;
        #pragma unroll
        for (int j = 0; j < 6; ++j) {
            const int ch  = tid + j * 128;
            const int mat = ch >> 8;              // 0..2
            const int tt  = (ch >> 4) & 15;       // 0..15
            const int seg = ch & 15;              // 0..15 (8 halfs each)
            const __half* src = g_proj[mat] + rowb
                              + (size_t)(s * 16 + tt) * H_ + seg * 8;
            cp16(dst + mat * 4096 + tt * 256 + seg * 16, src);
        }
    };

    load_stage(0); CP_COMMIT();
    load_stage(1); CP_COMMIT();
    load_stage(2); CP_COMMIT();

    float* o = out + (size_t)b * T_ * H_ + h;
    const __half* sm = reinterpret_cast<const __half*>(ssm);

    for (int c = 0; c < 32; ++c) {          // 32 chunks x 16 steps = T
        CP_WAIT(2);
        __syncthreads();

        load_stage(c + 3);                   // overrun lands in g_proj pad
        CP_COMMIT();

        const int sbuf = (c & 3) * (SC_STAGE / 2);   // offset in halfs
        float* ob = o + (size_t)(c * 16) * H_;
        #pragma unroll
        for (int i = 0; i < 16; ++i) {
            const int so = sbuf + i * 128 + tid;
            const float az = __half2float(sm[so])          + bzv;
            const float ar = __half2float(sm[so + 2048])   + brv;
            const float ah = __half2float(sm[so + 4096]);

            const float r  = tanh_hw(fmaf(hv, mrv, ar)) + 1.0f;
            const float z  = fmaf(0.5f,
                                  tanh_hw(0.5f * fmaf(hv, mzv, az)), 0.5f);
            const float ht = tanh_hw(fmaf(r, hv, ah));
            hv = fmaf(z, hv, (1.0f - z) * ht);

            __stcs(ob + (size_t)i * H_, hv);
        }
    }
}

// ---------------------------------------------------------------------------
extern "C" void kernel_launch(void* const* d_in, const int* in_sizes, int n_in,
                              void* d_out, int out_size)
{
    const float* x  = (const float*)d_in[0];
    const float* h0 = (const float*)d_in[1];
    const float* kz = (const float*)d_in[2];
    const float* kr = (const float*)d_in[3];
    const float* kh = (const float*)d_in[4];
    const float* mz = (const float*)d_in[5];
    const float* mr = (const float*)d_in[6];
    const float* bz = (const float*)d_in[7];
    const float* br = (const float*)d_in[8];
    float* out = (float*)d_out;

    cudaFuncSetAttribute(gemm_kernel,
                         cudaFuncAttributeMaxDynamicSharedMemorySize,
                         GEMM_SMEM);
    cudaFuncSetAttribute(scan_kernel,
                         cudaFuncAttributeMaxDynamicSharedMemorySize,
                         SC_SMEM);

    // convert x to fp16
    convert_x_kernel<<<(MTOT * D_ / 4) / 256, 256>>>(x);
    // transpose weights to fp16 [N][K]
    convert_w_kernel<<<dim3(16, 16, 3), 256>>>(kz, kr, kh);
    // 3 projections via mma.sync fp16: 256x128 tiles, warp 64x64, BK=64
    gemm_kernel<<<dim3(12, MTOT / 256), 256, GEMM_SMEM>>>();
    // recurrence (cp.async-staged)
    scan_kernel<<<(B_ * H_) / 128, 128, SC_SMEM>>>(h0, mz, mr, bz, br, out);
}

// round 17
// speedup vs baseline: 1.1174x; 1.1174x over previous
#include <cuda_runtime.h>
#include <cuda_fp16.h>
#include <cstdint>
#include <math.h>

#define B_   64
#define T_   512
#define D_   512
#define H_   512
#define MTOT (B_ * T_)          // 32768 GEMM rows

// ---------------------------------------------------------------------------
// Scratch (static __device__ — allocation-guard safe)
// ---------------------------------------------------------------------------
// projections xz, xr, xh in fp16, layout [b*t][h] (+64-step pad: the scan's
// cp.async pipeline prefetches up to 3 stages = 48 steps past the end).
__device__ __half g_proj[3][(size_t)MTOT * H_ + 64 * H_];
// fp16 x
__device__ __half g_A[(size_t)MTOT * D_];
// fp16 W^T (stored [N][K] K-major)
__device__ __half g_WT[3][H_ * D_];

// ---------------------------------------------------------------------------
// helpers
// ---------------------------------------------------------------------------
__device__ __forceinline__ uint32_t smem_u32(const void* p) {
    return (uint32_t)__cvta_generic_to_shared(p);
}

__device__ __forceinline__ void cp16(uint32_t dst, const void* src) {
    asm volatile("cp.async.cg.shared.global [%0], [%1], 16;"
                 :: "r"(dst), "l"(src) : "memory");
}
#define CP_COMMIT() asm volatile("cp.async.commit_group;" ::: "memory")
#define CP_WAIT(n)  asm volatile("cp.async.wait_group %0;" :: "n"(n) : "memory")

__device__ __forceinline__ void ldmatrix_x4(uint32_t& r0, uint32_t& r1,
                                            uint32_t& r2, uint32_t& r3,
                                            uint32_t addr) {
    asm volatile("ldmatrix.sync.aligned.m8n8.x4.shared.b16 {%0,%1,%2,%3}, [%4];"
                 : "=r"(r0), "=r"(r1), "=r"(r2), "=r"(r3) : "r"(addr));
}
__device__ __forceinline__ void mma16816(float* c, const uint32_t* a,
                                         const uint32_t* b) {
    asm volatile(
        "mma.sync.aligned.m16n8k16.row.col.f32.f16.f16.f32 "
        "{%0,%1,%2,%3}, {%4,%5,%6,%7}, {%8,%9}, {%0,%1,%2,%3};"
        : "+f"(c[0]), "+f"(c[1]), "+f"(c[2]), "+f"(c[3])
        : "r"(a[0]), "r"(a[1]), "r"(a[2]), "r"(a[3]), "r"(b[0]), "r"(b[1]));
}

// HW tanh (MUFU.TANH, sm_75+)
__device__ __forceinline__ float tanh_hw(float x) {
    float y;
    asm("tanh.approx.f32 %0, %1;" : "=f"(y) : "f"(x));
    return y;
}

// ---------------------------------------------------------------------------
// Kernel 1: convert x to fp16
// ---------------------------------------------------------------------------
__global__ __launch_bounds__(256)
void convert_x_kernel(const float* __restrict__ x) {
    size_t i = (size_t)blockIdx.x * blockDim.x + threadIdx.x;   // one float4
    float4 v = reinterpret_cast<const float4*>(x)[i];
    __half2* Hp = reinterpret_cast<__half2*>(g_A);
    Hp[2 * i]     = __halves2half2(__float2half_rn(v.x), __float2half_rn(v.y));
    Hp[2 * i + 1] = __halves2half2(__float2half_rn(v.z), __float2half_rn(v.w));
}

// ---------------------------------------------------------------------------
// Kernel 2: transpose weights to fp16 [N][K] via 32x33 smem tile
// (coalesced reads AND writes). grid = (16, 16, 3), block = 256.
// ---------------------------------------------------------------------------
__global__ __launch_bounds__(256)
void convert_w_kernel(const float* __restrict__ kz,
                      const float* __restrict__ kr,
                      const float* __restrict__ kh) {
    __shared__ float tile[32][33];
    const float* W = (blockIdx.z == 0) ? kz : (blockIdx.z == 1) ? kr : kh;
    const int k0 = blockIdx.y * 32;
    const int n0 = blockIdx.x * 32;
    const int tx = threadIdx.x & 31;
    const int ty = threadIdx.x >> 5;     // 0..7
    #pragma unroll
    for (int i = 0; i < 4; ++i)
        tile[ty + i * 8][tx] = W[(size_t)(k0 + ty + i * 8) * H_ + n0 + tx];
    __syncthreads();
    #pragma unroll
    for (int i = 0; i < 4; ++i) {
        int n = ty + i * 8;
        g_WT[blockIdx.z][(size_t)(n0 + n) * D_ + k0 + tx] =
            __float2half_rn(tile[tx][n]);
    }
}

// ---------------------------------------------------------------------------
// Kernel 3: fp16 GEMM via mma.sync.m16n8k16 — 2 CTAs/SM AND 128 MMAs/sync.
// CTA tile 128x128, 128 threads (4 warps: 2M x 2N, warp tile 64x64), BK=64.
// Combines R15's co-residency (bubble overlap) with R6/R16's long MMA
// bursts: per warp 4 k16-steps x 32 = 128 MMAs between syncs, NIT=8.
// 3-stage cp.async pipeline, 110.6 KB/CTA -> 2 CTAs = 221 KB/SM.
// Rows 128B data padded to 144B (conflict-free). Stage it+2 loads issued
// AFTER sync of iter it -> hazard-free. K order unchanged -> bit-identical.
// grid = (12, 256): x = mat*4 + ntile, y = mtile.
// ---------------------------------------------------------------------------
#define ROWB      144                        // smem row stride (bytes)
#define A_STAGE   (128 * ROWB)               // 18432 B
#define STAGE_B   (2 * A_STAGE)              // 36864 B (A + B)
#define GEMM_SMEM (3 * STAGE_B)              // 110592 B (x2 CTAs = 221 KB/SM)

__global__ __launch_bounds__(128, 2)
void gemm_kernel() {
    extern __shared__ __align__(128) char dsmem[];
    const uint32_t sbase = smem_u32(dsmem);

    const int tid  = threadIdx.x;
    const int lane = tid & 31;
    const int wid  = tid >> 5;          // 0..3
    const int wm   = (wid & 1) * 64;    // warp M offset in tile
    const int wn   = (wid >> 1) * 64;   // warp N offset in tile

    const int mat   = blockIdx.x >> 2;
    const int nBase = (blockIdx.x & 3) * 128;
    const int mBase = blockIdx.y * 128;

    const __half* Ap = g_A + (size_t)mBase * D_;
    const __half* Wp = g_WT[mat] + (size_t)nBase * D_;
    __half* C = g_proj[mat];

    // loaders: A and B each 128 rows x 8 chunks = 1024 chunks, 8/thread
    const int lrow = tid >> 3;       // base row (0..15), stepped by +16
    const int lseg = tid & 7;        // 16B chunk within 128B row
    auto load_tile = [&](int j) {    // j = k-tile index 0..7 (64 halfs each)
        const int kk = j * 64;
        const uint32_t sa = sbase + (j % 3) * STAGE_B;
        const uint32_t sb = sa + A_STAGE;
        #pragma unroll
        for (int i = 0; i < 8; ++i) {
            int row = lrow + i * 16;
            cp16(sa + row * ROWB + lseg * 16,
                 Ap + (size_t)row * D_ + kk + lseg * 8);
            cp16(sb + row * ROWB + lseg * 16,
                 Wp + (size_t)row * D_ + kk + lseg * 8);
        }
    };

    // ldmatrix per-lane offsets (row stride 144B; k16 halves 32B apart)
    const int a_off = (wm + (lane & 15)) * ROWB + (lane >> 4) * 16;
    const int b_off = (wn + (lane & 7) + ((lane >> 4) & 1) * 8) * ROWB
                    + ((lane >> 3) & 1) * 16;

    float acc[4][8][4];
    #pragma unroll
    for (int i = 0; i < 4; ++i)
        #pragma unroll
        for (int j = 0; j < 8; ++j)
            #pragma unroll
            for (int e = 0; e < 4; ++e) acc[i][j][e] = 0.0f;

    constexpr int NIT = 8;   // 512 / BK64
    load_tile(0); CP_COMMIT();
    load_tile(1); CP_COMMIT();

    for (int it = 0; it < NIT; ++it) {
        CP_WAIT(1);                // group 'it' (stage it) complete
        __syncthreads();           // all threads past iter it-1 compute

        // prefetch stage it+2 into buffer (it+2)%3 == (it-1)%3 — every
        // thread is past sync(it), hence past its it-1 compute: drained.
        if (it + 2 < NIT) load_tile(it + 2);
        CP_COMMIT();               // empty commits at tail keep wait math uniform

        const uint32_t sa = sbase + (it % 3) * STAGE_B;
        const uint32_t aB = sa + a_off;
        const uint32_t bB = sa + A_STAGE + b_off;

        #pragma unroll
        for (int ks = 0; ks < 4; ++ks) {          // four k16 steps in BK=64
            uint32_t af[4][4], bq[4][4];
            #pragma unroll
            for (int mt = 0; mt < 4; ++mt)
                ldmatrix_x4(af[mt][0], af[mt][1], af[mt][2], af[mt][3],
                            aB + mt * 16 * ROWB + ks * 32);
            #pragma unroll
            for (int np = 0; np < 4; ++np)        // each x4 = two n8 b-frags
                ldmatrix_x4(bq[np][0], bq[np][1], bq[np][2], bq[np][3],
                            bB + np * 16 * ROWB + ks * 32);
            #pragma unroll
            for (int mt = 0; mt < 4; ++mt)
                #pragma unroll
                for (int nt = 0; nt < 8; ++nt)
                    mma16816(acc[mt][nt], af[mt], &bq[nt >> 1][(nt & 1) * 2]);
        }
    }

    // epilogue: pack adjacent col pairs to half2 (4B stores)
    const int row0 = mBase + wm + (lane >> 2);
    const int col0 = nBase + wn + (lane & 3) * 2;
    #pragma unroll
    for (int mt = 0; mt < 4; ++mt) {
        #pragma unroll
        for (int nt = 0; nt < 8; ++nt) {
            __half* p = C + (size_t)(row0 + mt * 16) * H_ + col0 + nt * 8;
            *reinterpret_cast<__half2*>(p) =
                __floats2half2_rn(acc[mt][nt][0], acc[mt][nt][1]);
            *reinterpret_cast<__half2*>(p + 8 * H_) =
                __floats2half2_rn(acc[mt][nt][2], acc[mt][nt][3]);
        }
    }
}

// ---------------------------------------------------------------------------
// Kernel 4: diagonal recurrence scan, cp.async-staged (R12 version, frozen).
// ---------------------------------------------------------------------------
#define SC_STAGE 12288                     // 3 mats * 16 t * 256 B
#define SC_SMEM  (4 * SC_STAGE)            // 49152 B

__global__ __launch_bounds__(128)
void scan_kernel(const float* __restrict__ h0,
                 const float* __restrict__ mz, const float* __restrict__ mr,
                 const float* __restrict__ bz, const float* __restrict__ br,
                 float* __restrict__ out)
{
    extern __shared__ __align__(16) char ssm[];
    const uint32_t sb = smem_u32(ssm);
    const int tid = threadIdx.x;
    const int b   = blockIdx.x >> 2;        // 4 blocks per batch
    const int hb  = blockIdx.x & 3;
    const int h   = hb * 128 + tid;

    float hv = h0[(size_t)b * H_ + h];
    const float mzv = mz[h];
    const float mrv = mr[h];
    const float bzv = bz[h];
    const float brv = br[h];

    const size_t rowb = (size_t)b * T_ * H_ + (size_t)hb * 128;

    auto load_stage = [&](int s) {          // s = t-chunk index (16 steps)
        const uint32_t dst = sb + (s & 3) * SC_STAGE;
        #pragma unroll
        for (int j = 0; j < 6; ++j) {
            const int ch  = tid + j * 128;
            const int mat = ch >> 8;              // 0..2
            const int tt  = (ch >> 4) & 15;       // 0..15
            const int seg = ch & 15;              // 0..15 (8 halfs each)
            const __half* src = g_proj[mat] + rowb
                              + (size_t)(s * 16 + tt) * H_ + seg * 8;
            cp16(dst + mat * 4096 + tt * 256 + seg * 16, src);
        }
    };

    load_stage(0); CP_COMMIT();
    load_stage(1); CP_COMMIT();
    load_stage(2); CP_COMMIT();

    float* o = out + (size_t)b * T_ * H_ + h;
    const __half* sm = reinterpret_cast<const __half*>(ssm);

    for (int c = 0; c < 32; ++c) {          // 32 chunks x 16 steps = T
        CP_WAIT(2);
        __syncthreads();

        load_stage(c + 3);                   // overrun lands in g_proj pad
        CP_COMMIT();

        const int sbuf = (c & 3) * (SC_STAGE / 2);   // offset in halfs
        float* ob = o + (size_t)(c * 16) * H_;
        #pragma unroll
        for (int i = 0; i < 16; ++i) {
            const int so = sbuf + i * 128 + tid;
            const float az = __half2float(sm[so])          + bzv;
            const float ar = __half2float(sm[so + 2048])   + brv;
            const float ah = __half2float(sm[so + 4096]);

            const float r  = tanh_hw(fmaf(hv, mrv, ar)) + 1.0f;
            const float z  = fmaf(0.5f,
                                  tanh_hw(0.5f * fmaf(hv, mzv, az)), 0.5f);
            const float ht = tanh_hw(fmaf(r, hv, ah));
            hv = fmaf(z, hv, (1.0f - z) * ht);

            __stcs(ob + (size_t)i * H_, hv);
        }
    }
}

// ---------------------------------------------------------------------------
extern "C" void kernel_launch(void* const* d_in, const int* in_sizes, int n_in,
                              void* d_out, int out_size)
{
    const float* x  = (const float*)d_in[0];
    const float* h0 = (const float*)d_in[1];
    const float* kz = (const float*)d_in[2];
    const float* kr = (const float*)d_in[3];
    const float* kh = (const float*)d_in[4];
    const float* mz = (const float*)d_in[5];
    const float* mr = (const float*)d_in[6];
    const float* bz = (const float*)d_in[7];
    const float* br = (const float*)d_in[8];
    float* out = (float*)d_out;

    cudaFuncSetAttribute(gemm_kernel,
                         cudaFuncAttributeMaxDynamicSharedMemorySize,
                         GEMM_SMEM);
    cudaFuncSetAttribute(scan_kernel,
                         cudaFuncAttributeMaxDynamicSharedMemorySize,
                         SC_SMEM);

    // convert x to fp16
    convert_x_kernel<<<(MTOT * D_ / 4) / 256, 256>>>(x);
    // transpose weights to fp16 [N][K]
    convert_w_kernel<<<dim3(16, 16, 3), 256>>>(kz, kr, kh);
    // 3 projections: 128x128 tiles, 4 warps, warp 64x64, BK=64, 2 CTAs/SM
    gemm_kernel<<<dim3(12, MTOT / 128), 128, GEMM_SMEM>>>();
    // recurrence (cp.async-staged)
    scan_kernel<<<(B_ * H_) / 128, 128, SC_SMEM>>>(h0, mz, mr, bz, br, out);
}